// round 15
// baseline (speedup 1.0000x reference)
#include <cuda_runtime.h>
#include <cstdint>

// out = tanh(in @ Lr^T + br) + in @ Ld^T + bd + in
// Edge-flow scatter, grouped per target node:
//   per edge k (i=ei,j=ej): vr = wr_k*in[j]; vd = wd_k*in[i];
//     node j += (+vr, -vd);  node i += (-vr, +vd)
// One fire-and-forget vectorized cta-scope global reduction per endpoint.
//
// Critical-path-minimal structure:
//  - g_acc is zero at module load; the EPILOGUE re-zeroes it after reading,
//    so every call starts from zeros (deterministic, same work each call).
//    -> no zeroing prologue, no pre-scatter fence/sync.
//  - input values read via __ldg (L1) per edge -> no s_in staging, no first
//    __syncthreads. The only barrier is the post-scatter fence+sync that the
//    reductions require.
//
// Target-split independent CTAs: CTA = (batch, node-half); each CTA reads all
// edges (L2-broadcast) and fires only reductions landing in its owned half;
// it alone reads & re-zeroes that half.

#define NN 207
#define NE 1722
#define NPAIRS (NE / 2)      // 861
#define BATCH 64
#define THREADS 512
#define HALF0 104            // half 0 owns nodes [0,104), half 1 owns [104,207)

__device__ float2 g_acc[BATCH][NN];   // (reaction, diffusion); zero between calls

__device__ __forceinline__ float tanh_approx(float x) {
    float y;
    asm("tanh.approx.f32 %0, %1;" : "=f"(y) : "f"(x));
    return y;
}

__device__ __forceinline__ void red_cta_v2(float2* p, float a, float b) {
    asm volatile("red.relaxed.cta.global.add.v2.f32 [%0], {%1, %2};"
                 :: "l"(p), "f"(a), "f"(b) : "memory");
}

__global__ __launch_bounds__(THREADS)
void rd_k(const float* __restrict__ in,
          const float* __restrict__ wr,
          const float* __restrict__ wd,
          const float* __restrict__ br,
          const float* __restrict__ bd,
          const int*   __restrict__ ei,
          const int*   __restrict__ ej,
          float* __restrict__ out) {
    const int tid   = threadIdx.x;
    const int batch = blockIdx.x >> 1;
    const int half  = blockIdx.x & 1;
    const int n_lo  = half ? HALF0 : 0;
    const int n_hi  = half ? NN : HALF0;
    const float* __restrict__ row = in + batch * NN;

    // ---- prefetch edge pairs (high-MLP LDG.64 burst) ----
    const int kA = 2 * tid;                       // pairs [0,512)
    int2 iA = *reinterpret_cast<const int2*>(&ei[kA]);
    int2 jA = *reinterpret_cast<const int2*>(&ej[kA]);
    float2 rA = *reinterpret_cast<const float2*>(&wr[kA]);
    float2 dA = *reinterpret_cast<const float2*>(&wd[kA]);
    const bool hasB = (tid + THREADS) < NPAIRS;   // pairs [512,861)
    int2 iB; int2 jB; float2 rB; float2 dB;
    if (hasB) {
        const int kB = 2 * (tid + THREADS);
        iB = *reinterpret_cast<const int2*>(&ei[kB]);
        jB = *reinterpret_cast<const int2*>(&ej[kB]);
        rB = *reinterpret_cast<const float2*>(&wr[kB]);
        dB = *reinterpret_cast<const float2*>(&wd[kB]);
    }

    // ---- prefetch epilogue operands (latency hides under scatter) ----
    const int n_out = n_lo + tid;
    const bool owns = (n_out < n_hi);
    float brn = 0.0f, bdn = 0.0f, xin = 0.0f;
    if (owns) {
        brn = br[n_out];
        bdn = bd[n_out];
        xin = __ldg(&row[n_out]);
    }

    // ---- scatter: one v2 cta-scope global red per in-half endpoint ----
    // No barrier needed before this: g_acc is already zero (epilogue of the
    // previous call / module load), and inputs are read directly via L1.
    #define PROCESS(i_, j_, wr_, wd_)                                    \
    do {                                                                 \
        const int i = (i_), j = (j_);                                    \
        const float vr = (wr_) * __ldg(&row[j]);                         \
        const float vd = (wd_) * __ldg(&row[i]);                         \
        if ((j >= HALF0) == half) red_cta_v2(&g_acc[batch][j],  vr, -vd);\
        if ((i >= HALF0) == half) red_cta_v2(&g_acc[batch][i], -vr,  vd);\
    } while (0)

    PROCESS(iA.x, jA.x, rA.x, dA.x);
    PROCESS(iA.y, jA.y, rA.y, dA.y);
    if (hasB) {
        PROCESS(iB.x, jB.x, rB.x, dB.x);
        PROCESS(iB.y, jB.y, rB.y, dB.y);
    }
    #undef PROCESS

    __threadfence_block();    // this thread's reds performed (cta scope) ...
    __syncthreads();          // ... and all threads' reds ordered before reads

    // ---- epilogue: read back (L2), finalize, re-zero for next call ----
    if (owns) {
        float2* slot = &g_acc[batch][n_out];
        const float2 acc = __ldcg(slot);
        __stcg(slot, make_float2(0.0f, 0.0f));   // restore invariant
        out[batch * NN + n_out] =
            tanh_approx(acc.x + brn) + acc.y + bdn + xin;
    }
}

extern "C" void kernel_launch(void* const* d_in, const int* in_sizes, int n_in,
                              void* d_out, int out_size) {
    const float* in_ = (const float*)d_in[0];
    const float* wr  = (const float*)d_in[1];
    const float* wd  = (const float*)d_in[2];
    const float* br  = (const float*)d_in[3];
    const float* bd  = (const float*)d_in[4];
    const int*   ei  = (const int*)d_in[5];
    const int*   ej  = (const int*)d_in[6];
    float* out = (float*)d_out;

    rd_k<<<BATCH * 2, THREADS>>>(in_, wr, wd, br, bd, ei, ej, out);
}

// round 16
// speedup vs baseline: 1.0295x; 1.0295x over previous
#include <cuda_runtime.h>
#include <cuda_fp16.h>
#include <cstdint>

// out = tanh(in @ Lr^T + br) + in @ Ld^T + bd + in
// Edge-flow scatter, grouped per target node and packed:
//   per edge k (i=ei,j=ej): vr = wr_k*in[j]; vd = wd_k*in[i];
//     node j += (+vr, -vd);  node i += (-vr, +vd)
// Accumulators are __half2 (r,d): ONE 4-byte smem atomic per endpoint
// (1722 active lanes/CTA — the decomposition floor: 3444 endpoint updates
// per batch split across 2 CTAs).
//
// Target-split independent CTAs: CTA = (batch, node-half); each CTA reads all
// edges (L2-broadcast) and applies only updates landing in its owned half.
// Accumulators compacted to the owned half (104 entries).

#define NN 207
#define NE 1722
#define NPAIRS (NE / 2)      // 861
#define BATCH 64
#define THREADS 512
#define HALF0 104            // half 0 owns nodes [0,104), half 1 owns [104,207)
#define MAXOWN 104

__device__ __forceinline__ float tanh_approx(float x) {
    float y;
    asm("tanh.approx.f32 %0, %1;" : "=f"(y) : "f"(x));
    return y;
}

__global__ __launch_bounds__(THREADS)
void rd_k(const float* __restrict__ in,
          const float* __restrict__ wr,
          const float* __restrict__ wd,
          const float* __restrict__ br,
          const float* __restrict__ bd,
          const int*   __restrict__ ei,
          const int*   __restrict__ ej,
          float* __restrict__ out) {
    __shared__ float   s_in[NN];
    __shared__ __half2 s_rd[MAXOWN];     // packed (reaction, diffusion), owned half only

    const int tid   = threadIdx.x;
    const int batch = blockIdx.x >> 1;
    const int half  = blockIdx.x & 1;
    const int n_lo  = half ? HALF0 : 0;
    const unsigned n_cnt = half ? (NN - HALF0) : HALF0;   // 103 / 104

    // ---- prefetch edge pairs (high-MLP LDG.64 burst) ----
    const int kA = 2 * tid;                       // pairs [0,512)
    int2 iA = *reinterpret_cast<const int2*>(&ei[kA]);
    int2 jA = *reinterpret_cast<const int2*>(&ej[kA]);
    float2 rA = *reinterpret_cast<const float2*>(&wr[kA]);
    float2 dA = *reinterpret_cast<const float2*>(&wd[kA]);
    const bool hasB = (tid + THREADS) < NPAIRS;   // pairs [512,861)
    int2 iB; int2 jB; float2 rB; float2 dB;
    if (hasB) {
        const int kB = 2 * (tid + THREADS);
        iB = *reinterpret_cast<const int2*>(&ei[kB]);
        jB = *reinterpret_cast<const int2*>(&ej[kB]);
        rB = *reinterpret_cast<const float2*>(&wr[kB]);
        dB = *reinterpret_cast<const float2*>(&wd[kB]);
    }

    // ---- prefetch epilogue biases (latency hides under scatter) ----
    const int n_out = n_lo + tid;
    const bool owns = (unsigned)tid < n_cnt;
    float brn = 0.0f, bdn = 0.0f;
    if (owns) {
        brn = br[n_out];
        bdn = bd[n_out];
    }

    // ---- load input row + zero owned accumulators ----
    if (tid < NN) s_in[tid] = in[batch * NN + tid];
    if (tid < MAXOWN) s_rd[tid] = __floats2half2_rn(0.0f, 0.0f);
    __syncthreads();

    // ---- scatter: ONE packed half2 atomic per owned endpoint ----
    #define PROCESS(i_, j_, wr_, wd_)                               \
    do {                                                            \
        const int i = (i_), j = (j_);                               \
        const float vr = (wr_) * s_in[j];                           \
        const float vd = (wd_) * s_in[i];                           \
        const unsigned jl = (unsigned)(j - n_lo);                   \
        const unsigned il = (unsigned)(i - n_lo);                   \
        if (jl < n_cnt)                                             \
            atomicAdd(&s_rd[jl], __floats2half2_rn( vr, -vd));      \
        if (il < n_cnt)                                             \
            atomicAdd(&s_rd[il], __floats2half2_rn(-vr,  vd));      \
    } while (0)

    PROCESS(iA.x, jA.x, rA.x, dA.x);
    PROCESS(iA.y, jA.y, rA.y, dA.y);
    if (hasB) {
        PROCESS(iB.x, jB.x, rB.x, dB.x);
        PROCESS(iB.y, jB.y, rB.y, dB.y);
    }
    #undef PROCESS
    __syncthreads();

    // ---- epilogue ----
    if (owns) {
        const float2 acc = __half22float2(s_rd[tid]);
        __stcs(&out[batch * NN + n_out],
               tanh_approx(acc.x + brn) + acc.y + bdn + s_in[n_out]);
    }
}

extern "C" void kernel_launch(void* const* d_in, const int* in_sizes, int n_in,
                              void* d_out, int out_size) {
    const float* in_ = (const float*)d_in[0];
    const float* wr  = (const float*)d_in[1];
    const float* wd  = (const float*)d_in[2];
    const float* br  = (const float*)d_in[3];
    const float* bd  = (const float*)d_in[4];
    const int*   ei  = (const int*)d_in[5];
    const int*   ej  = (const int*)d_in[6];
    float* out = (float*)d_out;

    rd_k<<<BATCH * 2, THREADS>>>(in_, wr, wd, br, bd, ei, ej, out);
}